// round 15
// baseline (speedup 1.0000x reference)
#include <cuda_runtime.h>
#include <cuda_bf16.h>

// Problem constants:
//   B = 128 rows, L = 262144 input cols
//   CROP_NUM = 26214, OUT_LEN = 235930
//   out[i, j] = audio[i, j]             for j <  starts[i]
//   out[i, j] = audio[i, j + CROP_NUM]  for j >= starts[i]
//
// Final configuration after full sweep on sm_103a:
//   - one-shot 2D grid (58 x 128), blockIdx.y = row -> uniform `start`,
//     no div/mod, no row-straddle path (best measured family)
//   - ILP 4 (2 best-tied, 8 regresses), 256 threads
//   - DEFAULT loads/stores (all of __stcs / evict_last / __stwt within
//     noise or worse; persistent grid regresses)
//   - alignment-aware loads: j0 = pre (mod 4) and CROP_NUM = 2 (mod 4),
//     so per row parity exactly one contiguous branch is 16B-aligned ->
//     LDG.128 there, 2x LDG.64 on the other.
// DRAM R/W turnaround (~70% of spec at 50/50 mix) is the measured wall.

#define L_IN     262144u
#define CROP_NUM 26214u
#define OUT_LEN  235930u
#define ROW_VECS 58982u          // full aligned float4 vectors per row
#define BLK_VECS 1024u           // 256 threads * ILP 4
#define GRID_X   58u             // ceil(58982 / 1024)

__device__ __forceinline__ float4 ld_f4_16B(const float* p)   // 16B-aligned
{
    return __ldg(reinterpret_cast<const float4*>(p));
}

__device__ __forceinline__ float4 ld_f4_8B(const float* p)    // 8B-aligned
{
    const float2* q = reinterpret_cast<const float2*>(p);
    float2 a = __ldg(q);
    float2 b = __ldg(q + 1);
    return make_float4(a.x, a.y, b.x, b.y);
}

__global__ __launch_bounds__(256)
void Crop_21345987461560_kernel(const float* __restrict__ audio,
                                const int*   __restrict__ starts,
                                float*       __restrict__ out)
{
    const unsigned int row = blockIdx.y;
    const unsigned int pre = (row & 1u) << 1;                 // 0 or 2
    const unsigned int start = (unsigned int)__ldg(&starts[row]);  // uniform
    const float* __restrict__ rowp = audio + (size_t)row * L_IN;

    // row*OUT_LEN + pre is a multiple of 4 -> aligned float4 view.
    float4* __restrict__ out4 =
        reinterpret_cast<float4*>(out + (size_t)row * OUT_LEN + pre);

    const unsigned int v0 = blockIdx.x * BLK_VECS + threadIdx.x;

    #pragma unroll
    for (unsigned int k = 0; k < 4u; ++k) {
        unsigned int v = v0 + k * 256u;
        if (v < ROW_VECS) {
            unsigned int j0 = pre + v * 4u;                   // = pre (mod 4)
            float4 r;
            if (j0 >= start) {
                // Post-crop: src = j0 + CROP_NUM. CROP_NUM = 2 (mod 4):
                // even rows (pre=0) -> 8B aligned; odd rows (pre=2) -> 16B.
                const float* p = rowp + j0 + CROP_NUM;
                r = pre ? ld_f4_16B(p) : ld_f4_8B(p);
            } else if (j0 + 3u < start) {
                // Pre-crop: src = j0.
                // even rows -> 16B aligned; odd rows -> 8B.
                const float* p = rowp + j0;
                r = pre ? ld_f4_8B(p) : ld_f4_16B(p);
            } else {
                // Straddles the crop boundary (one vector per row): scalar
                unsigned int j;
                j = j0;      r.x = __ldg(&rowp[j + (j >= start ? CROP_NUM : 0u)]);
                j = j0 + 1u; r.y = __ldg(&rowp[j + (j >= start ? CROP_NUM : 0u)]);
                j = j0 + 2u; r.z = __ldg(&rowp[j + (j >= start ? CROP_NUM : 0u)]);
                j = j0 + 3u; r.w = __ldg(&rowp[j + (j >= start ? CROP_NUM : 0u)]);
            }
            out4[v] = r;
        }
    }

    // 2 leftover scalar elements per row: prefix (j=0,1) on odd rows,
    // suffix (j=OUT_LEN-2, OUT_LEN-1) on even rows.
    if (blockIdx.x == 0 && threadIdx.x < 2u) {
        unsigned int j = (row & 1u) ? threadIdx.x
                                    : (OUT_LEN - 2u + threadIdx.x);
        out[(size_t)row * OUT_LEN + j] =
            __ldg(&rowp[j + (j >= start ? CROP_NUM : 0u)]);
    }
}

extern "C" void kernel_launch(void* const* d_in, const int* in_sizes, int n_in,
                              void* d_out, int out_size)
{
    const float* audio  = (const float*)d_in[0];   // [128, 262144] float32
    const int*   starts = (const int*)d_in[1];     // [128] int32
    float*       out    = (float*)d_out;           // [128, 235930] float32

    dim3 grid(GRID_X, 128u, 1u);                   // 58 x 128 = 7424 blocks
    Crop_21345987461560_kernel<<<grid, 256>>>(audio, starts, out);
}